// round 1
// baseline (speedup 1.0000x reference)
#include <cuda_runtime.h>

// APPNP: h_{t+1} = 0.9 * norm ⊙ (A^T (norm ⊙ h_t)) + 0.1 * feat0, K=10
// State kept as g_t = norm ⊙ h_t so each iteration is:
//   scatter:  agg[dst] += g[src]                (vector RED, fire-and-forget)
//   update :  g = 0.9*norm^2*agg + 0.1*norm*f0  (and re-zero agg in place)
// Final iteration writes h = 0.9*norm*agg + 0.1*feat0 to d_out.

#define NMAX 100000
#define DF   64
#define DF4  (DF / 4)
#define EMAX 1000000
#define KITER 10

__device__ float g_g[NMAX * DF];    // norm-scaled state
__device__ float g_agg[NMAX * DF];  // scatter accumulator
__device__ float g_norm[NMAX];
__device__ int   g_deg[NMAX];

// Zero agg (float4-wide) and deg.
__global__ void k_zero(int n) {
    int i = blockIdx.x * blockDim.x + threadIdx.x;
    int tot4 = n * DF4;
    if (i < tot4) {
        reinterpret_cast<float4*>(g_agg)[i] = make_float4(0.f, 0.f, 0.f, 0.f);
    }
    if (i < n) g_deg[i] = 0;
}

// In-degree histogram.
__global__ void k_deg(const int* __restrict__ dst, int e) {
    int i = blockIdx.x * blockDim.x + threadIdx.x;
    if (i < e) atomicAdd(&g_deg[dst[i]], 1);
}

// norm = deg^{-1/2}, deg clamped to >= 1.
__global__ void k_norm(int n) {
    int i = blockIdx.x * blockDim.x + threadIdx.x;
    if (i < n) g_norm[i] = rsqrtf(fmaxf((float)g_deg[i], 1.0f));
}

// g_0 = norm ⊙ feat
__global__ void k_init(const float* __restrict__ feat, int n) {
    int i = blockIdx.x * blockDim.x + threadIdx.x;
    if (i < n * DF4) {
        int row = i >> 4;
        float nm = g_norm[row];
        float4 f = reinterpret_cast<const float4*>(feat)[i];
        f.x *= nm; f.y *= nm; f.z *= nm; f.w *= nm;
        reinterpret_cast<float4*>(g_g)[i] = f;
    }
}

// Scatter: each thread owns one float4 chunk of one edge's message.
// 16 consecutive threads cover one edge's 64-float row (256B, coalesced).
__global__ void k_scatter(const int* __restrict__ src,
                          const int* __restrict__ dst, int e) {
    long long i = (long long)blockIdx.x * blockDim.x + threadIdx.x;
    if (i >= (long long)e * DF4) return;
    int eid = (int)(i >> 4);
    int c   = (int)(i & 15);
    int s = __ldg(&src[eid]);
    int d = __ldg(&dst[eid]);
    float4 v = reinterpret_cast<const float4*>(g_g)[s * DF4 + c];
    float* p = &g_agg[(long long)d * DF + c * 4];
    // Vector reduction to global (no return value) — 4 floats per instruction.
    asm volatile("red.global.add.v4.f32 [%0], {%1, %2, %3, %4};"
                 :: "l"(p), "f"(v.x), "f"(v.y), "f"(v.z), "f"(v.w)
                 : "memory");
}

// Mid-loop update: g = 0.9*norm^2*agg + 0.1*norm*feat0 ; agg <- 0 (in place,
// same cacheline already resident in L2 — cheaper than a separate memset).
__global__ void k_update(const float* __restrict__ feat, int n) {
    int i = blockIdx.x * blockDim.x + threadIdx.x;
    if (i < n * DF4) {
        int row = i >> 4;
        float nm = g_norm[row];
        float c1 = 0.9f * nm * nm;
        float c2 = 0.1f * nm;
        float4 a = reinterpret_cast<float4*>(g_agg)[i];
        float4 f = reinterpret_cast<const float4*>(feat)[i];
        float4 g;
        g.x = c1 * a.x + c2 * f.x;
        g.y = c1 * a.y + c2 * f.y;
        g.z = c1 * a.z + c2 * f.z;
        g.w = c1 * a.w + c2 * f.w;
        reinterpret_cast<float4*>(g_g)[i] = g;
        reinterpret_cast<float4*>(g_agg)[i] = make_float4(0.f, 0.f, 0.f, 0.f);
    }
}

// Final step: h = 0.9*norm*agg + 0.1*feat0 written to d_out.
__global__ void k_final(const float* __restrict__ feat,
                        float* __restrict__ out, int n) {
    int i = blockIdx.x * blockDim.x + threadIdx.x;
    if (i < n * DF4) {
        int row = i >> 4;
        float nm = g_norm[row];
        float c1 = 0.9f * nm;
        float4 a = reinterpret_cast<float4*>(g_agg)[i];
        float4 f = reinterpret_cast<const float4*>(feat)[i];
        float4 h;
        h.x = c1 * a.x + 0.1f * f.x;
        h.y = c1 * a.y + 0.1f * f.y;
        h.z = c1 * a.z + 0.1f * f.z;
        h.w = c1 * a.w + 0.1f * f.w;
        reinterpret_cast<float4*>(out)[i] = h;
    }
}

extern "C" void kernel_launch(void* const* d_in, const int* in_sizes, int n_in,
                              void* d_out, int out_size) {
    const float* feat = (const float*)d_in[0];
    const int*   src  = (const int*)d_in[1];
    const int*   dst  = (const int*)d_in[2];
    float*       out  = (float*)d_out;

    int n = in_sizes[0] / DF;   // 100000
    int e = in_sizes[1];        // 1000000

    const int T = 256;
    int blk_nd4 = (n * DF4 + T - 1) / T;                        // node*chunk grid
    int blk_e   = (e + T - 1) / T;
    int blk_n   = (n + T - 1) / T;
    long long sc_threads = (long long)e * DF4;
    int blk_sc  = (int)((sc_threads + T - 1) / T);              // 62500 blocks

    k_zero<<<blk_nd4, T>>>(n);
    k_deg<<<blk_e, T>>>(dst, e);
    k_norm<<<blk_n, T>>>(n);
    k_init<<<blk_nd4, T>>>(feat, n);

    for (int t = 0; t < KITER; ++t) {
        k_scatter<<<blk_sc, T>>>(src, dst, e);
        if (t < KITER - 1) {
            k_update<<<blk_nd4, T>>>(feat, n);
        } else {
            k_final<<<blk_nd4, T>>>(feat, out, n);
        }
    }
}

// round 2
// speedup vs baseline: 1.1584x; 1.1584x over previous
#include <cuda_runtime.h>

// APPNP, K=10:  g_{t+1} = 0.9*norm^2 * (sum_{(s->v) in E} g_t[s]) + 0.1*norm*feat0
// where g = norm ⊙ h. Final: h = 0.9*norm*agg + 0.1*feat0.
//
// Strategy: build CSR (edges counting-sorted by dst) once per call, then each
// iteration is a pure gather — one warp per destination node, register
// accumulation, single write. No atomics in the hot loop, no agg array,
// update fused into the gather. Loop working set (g_a+g_b+feat ~77MB) is
// L2-resident.

#define NMAX  100000
#define DF    64
#define DF2   (DF / 2)
#define DF4   (DF / 4)
#define EMAX  1000000
#define KITER 10
#define SCAN_T 1024

__device__ float g_a[NMAX * DF];     // ping
__device__ float g_b[NMAX * DF];     // pong
__device__ float g_norm[NMAX];
__device__ int   g_deg[NMAX];
__device__ int   g_rowptr[NMAX + 1];
__device__ int   g_cursor[NMAX];
__device__ int   g_srcs[EMAX];       // src ids sorted by dst bucket

// ---------------------------------------------------------------- build ----

__global__ void k_zero(int n) {
    int i = blockIdx.x * blockDim.x + threadIdx.x;
    if (i < n) { g_deg[i] = 0; g_cursor[i] = 0; }
}

__global__ void k_deg(const int* __restrict__ dst, int e) {
    int i = blockIdx.x * blockDim.x + threadIdx.x;
    if (i < e) atomicAdd(&g_deg[dst[i]], 1);
}

// Single-block exclusive scan of g_deg -> g_rowptr; also norm = deg^{-1/2}.
__global__ void k_scan(int n, int e) {
    __shared__ int sums[SCAN_T];
    int t = threadIdx.x;
    int chunk = (n + SCAN_T - 1) / SCAN_T;
    int start = t * chunk;
    int end   = min(start + chunk, n);
    int s = 0;
    for (int i = start; i < end; ++i) s += g_deg[i];
    sums[t] = s;
    __syncthreads();
    // inclusive Hillis-Steele over 1024 partials
    for (int off = 1; off < SCAN_T; off <<= 1) {
        int x = (t >= off) ? sums[t - off] : 0;
        __syncthreads();
        sums[t] += x;
        __syncthreads();
    }
    int run = sums[t] - s;  // exclusive prefix of my chunk
    for (int i = start; i < end; ++i) {
        int d = g_deg[i];
        g_rowptr[i] = run;
        g_norm[i]   = rsqrtf(fmaxf((float)d, 1.0f));
        run += d;
    }
    if (t == 0) g_rowptr[n] = e;
}

// Counting-sort fill: place each edge's src into its dst bucket.
__global__ void k_fill(const int* __restrict__ src,
                       const int* __restrict__ dst, int e) {
    int i = blockIdx.x * blockDim.x + threadIdx.x;
    if (i < e) {
        int d = dst[i];
        int pos = g_rowptr[d] + atomicAdd(&g_cursor[d], 1);
        g_srcs[pos] = src[i];
    }
}

// g_0 = norm ⊙ feat  (into g_a)
__global__ void k_init(const float* __restrict__ feat, int n) {
    int i = blockIdx.x * blockDim.x + threadIdx.x;
    if (i < n * DF4) {
        int row = i >> 4;
        float nm = g_norm[row];
        float4 f = reinterpret_cast<const float4*>(feat)[i];
        f.x *= nm; f.y *= nm; f.z *= nm; f.w *= nm;
        reinterpret_cast<float4*>(g_a)[i] = f;
    }
}

// ----------------------------------------------------------------- loop ----

// One warp per destination node. Each lane owns 2 columns (float2, 8B), so a
// warp's row access is one coalesced 256B transaction per incoming edge.
// flip: 0 -> read g_a write g_b, 1 -> read g_b write g_a.
// last: write h = 0.9*norm*acc + 0.1*feat to `out` instead.
__global__ void k_prop(const float* __restrict__ feat,
                       float* __restrict__ out,
                       int n, int flip, int last) {
    int gt   = blockIdx.x * blockDim.x + threadIdx.x;
    int v    = gt >> 5;           // node = warp id
    int lane = gt & 31;
    if (v >= n) return;

    const float2* gin  = reinterpret_cast<const float2*>(flip ? g_b : g_a);
    float2*       gout = reinterpret_cast<float2*>(flip ? g_a : g_b);

    int start = g_rowptr[v];
    int end   = g_rowptr[v + 1];

    float ax = 0.f, ay = 0.f;
    for (int base = start; base < end; base += 32) {
        int idx = base + lane;
        int s   = (idx < end) ? g_srcs[idx] : 0;
        int cnt = min(32, end - base);
        int j = 0;
        // unroll by 2 for MLP on the row loads
        for (; j + 1 < cnt; j += 2) {
            int s0 = __shfl_sync(0xffffffff, s, j);
            int s1 = __shfl_sync(0xffffffff, s, j + 1);
            float2 v0 = gin[s0 * DF2 + lane];
            float2 v1 = gin[s1 * DF2 + lane];
            ax += v0.x; ay += v0.y;
            ax += v1.x; ay += v1.y;
        }
        if (j < cnt) {
            int s0 = __shfl_sync(0xffffffff, s, j);
            float2 v0 = gin[s0 * DF2 + lane];
            ax += v0.x; ay += v0.y;
        }
    }

    float nm = g_norm[v];
    float2 f = reinterpret_cast<const float2*>(feat)[v * DF2 + lane];
    float2 o;
    if (!last) {
        float c1 = 0.9f * nm * nm;
        float c2 = 0.1f * nm;
        o.x = c1 * ax + c2 * f.x;
        o.y = c1 * ay + c2 * f.y;
        gout[v * DF2 + lane] = o;
    } else {
        float c1 = 0.9f * nm;
        o.x = c1 * ax + 0.1f * f.x;
        o.y = c1 * ay + 0.1f * f.y;
        reinterpret_cast<float2*>(out)[v * DF2 + lane] = o;
    }
}

// ---------------------------------------------------------------- launch ----

extern "C" void kernel_launch(void* const* d_in, const int* in_sizes, int n_in,
                              void* d_out, int out_size) {
    const float* feat = (const float*)d_in[0];
    const int*   src  = (const int*)d_in[1];
    const int*   dst  = (const int*)d_in[2];
    float*       out  = (float*)d_out;

    int n = in_sizes[0] / DF;   // 100000
    int e = in_sizes[1];        // 1000000

    const int T = 256;
    int blk_n   = (n + T - 1) / T;
    int blk_e   = (e + T - 1) / T;
    int blk_nd4 = (n * DF4 + T - 1) / T;
    int blk_p   = (n * 32 + T - 1) / T;     // warp per node

    // CSR build (per call; graph-capturable, no allocs)
    k_zero<<<blk_n, T>>>(n);
    k_deg<<<blk_e, T>>>(dst, e);
    k_scan<<<1, SCAN_T>>>(n, e);
    k_fill<<<blk_e, T>>>(src, dst, e);
    k_init<<<blk_nd4, T>>>(feat, n);

    // Propagation: ping-pong g_a <-> g_b, final iter writes d_out.
    for (int t = 0; t < KITER; ++t) {
        int flip = t & 1;
        int last = (t == KITER - 1);
        k_prop<<<blk_p, T>>>(feat, out, n, flip, last);
    }
}